// round 4
// baseline (speedup 1.0000x reference)
#include <cuda_runtime.h>
#include <cuda_bf16.h>

#define H  100000
#define E  200000
#define NI 1000000

typedef unsigned long long u64;

// ---------------- scratch (device globals: no allocations allowed) ----------
__device__ float4 g_edge_acc[E * 32];   // [E][128] as float4
__device__ float  g_edge_cnt[E];
__device__ float4 g_edge_msg[E * 32];   // [E][128]
__device__ float4 g_node_acc[H * 32];   // [H][128]
__device__ float  g_node_cnt[H];

// transposed weights: [k][out] so the k-loop load is lane-coalesced float4
__device__ float4 g_W1t[192 * 32];      // from We1 [128][192]
__device__ float4 g_W2t[128 * 32];      // from We2 [128][128]
__device__ float4 g_Wpt[128 * 32];      // from Wp
__device__ float4 g_Wn1t[128 * 32];
__device__ float4 g_Wn2t[128 * 32];

// ---------------- packed f32x2 fma ------------------------------------------
__device__ __forceinline__ u64 ffma2(u64 a, u64 b, u64 c) {
    u64 d;
    asm("fma.rn.f32x2 %0, %1, %2, %3;" : "=l"(d) : "l"(a), "l"(b), "l"(c));
    return d;
}
__device__ __forceinline__ float2 unpack2(u64 v) {
    float2 r;
    asm("mov.b64 {%0, %1}, %2;" : "=f"(r.x), "=f"(r.y) : "l"(v));
    return r;
}

// ---------------- zero accumulators -----------------------------------------
__global__ void k_zero() {
    int i = blockIdx.x * blockDim.x + threadIdx.x;
    float4 z = make_float4(0.f, 0.f, 0.f, 0.f);
    if (i < E * 32) g_edge_acc[i] = z;
    if (i < H * 32) g_node_acc[i] = z;
    if (i < E) g_edge_cnt[i] = 0.f;
    if (i < H) g_node_cnt[i] = 0.f;
}

// ---------------- transpose weights -----------------------------------------
__global__ void k_prep(const float* __restrict__ We1, const float* __restrict__ We2,
                       const float* __restrict__ Wp,  const float* __restrict__ Wn1,
                       const float* __restrict__ Wn2) {
    int i = blockIdx.x * blockDim.x + threadIdx.x;
    if (i < 192 * 128) {
        int k = i / 128, o = i % 128;
        ((float*)g_W1t)[i] = We1[o * 192 + k];
    }
    if (i < 128 * 128) {
        int k = i / 128, o = i % 128;
        ((float*)g_W2t)[i]  = We2[o * 128 + k];
        ((float*)g_Wpt)[i]  = Wp [o * 128 + k];
        ((float*)g_Wn1t)[i] = Wn1[o * 128 + k];
        ((float*)g_Wn2t)[i] = Wn2[o * 128 + k];
    }
}

// ---------------- vectorized global reduction helper ------------------------
__device__ __forceinline__ void red_add_v4(float* p, float4 v) {
    unsigned long long a = (unsigned long long)__cvta_generic_to_global(p);
    asm volatile("red.global.add.v4.f32 [%0], {%1, %2, %3, %4};"
                 :: "l"(a), "f"(v.x), "f"(v.y), "f"(v.z), "f"(v.w) : "memory");
}

// ---------------- scatter node -> edge ---------------------------------------
__global__ void k_scat_ne(const float4* __restrict__ xh,
                          const int* __restrict__ fg, const int* __restrict__ res) {
    int t = blockIdx.x * blockDim.x + threadIdx.x;   // < NI*32 = 32M
    int i = t >> 5, c = t & 31;
    int f = fg[i], r = res[i];
    float4 v = xh[f * 32 + c];
    red_add_v4((float*)&g_edge_acc[r * 32 + c], v);
    if (c == 0) atomicAdd(&g_edge_cnt[r], 1.f);
}

// ---------------- scatter edge -> node ---------------------------------------
__global__ void k_scat_en(const int* __restrict__ fg, const int* __restrict__ res) {
    int t = blockIdx.x * blockDim.x + threadIdx.x;
    int i = t >> 5, c = t & 31;
    int f = fg[i], r = res[i];
    float4 v = g_edge_msg[r * 32 + c];
    red_add_v4((float*)&g_node_acc[f * 32 + c], v);
    if (c == 0) atomicAdd(&g_node_cnt[f], 1.f);
}

// ---------------- edge MLP (packed f32x2) ------------------------------------
// 256 thr = 8 warps. Each warp: 4 edges, lane owns out-dims [4l,4l+4) as 2 pairs.
// Activations staged DUPLICATED (s,s) so LDS.64 gives the f32x2 broadcast operand.
// Hidden layer reuses the same warp-private smem region (all reads precede writes).
__global__ void __launch_bounds__(256) k_edge_mlp(const float4* __restrict__ attr,
                                                  const float* __restrict__ be1,
                                                  const float* __restrict__ be2) {
    __shared__ float2 s_in[8][4][192];   // 48KB, warp-private [4][192] regions
    int warp = threadIdx.x >> 5, lane = threadIdx.x & 31;
    int e0 = (blockIdx.x * 8 + warp) * 4;

    // stage inputs duplicated: mean of members + edge attr
    #pragma unroll
    for (int j = 0; j < 4; j++) {
        int e = e0 + j;
        float inv = 1.f / fmaxf(g_edge_cnt[e], 1.f);
        float4 a = g_edge_acc[e * 32 + lane];
        s_in[warp][j][4*lane+0] = make_float2(a.x*inv, a.x*inv);
        s_in[warp][j][4*lane+1] = make_float2(a.y*inv, a.y*inv);
        s_in[warp][j][4*lane+2] = make_float2(a.z*inv, a.z*inv);
        s_in[warp][j][4*lane+3] = make_float2(a.w*inv, a.w*inv);
        if (lane < 16) {
            float4 t = attr[e * 16 + lane];
            s_in[warp][j][128+4*lane+0] = make_float2(t.x, t.x);
            s_in[warp][j][128+4*lane+1] = make_float2(t.y, t.y);
            s_in[warp][j][128+4*lane+2] = make_float2(t.z, t.z);
            s_in[warp][j][128+4*lane+3] = make_float2(t.w, t.w);
        }
    }
    __syncwarp();

    // GEMM1: [4 x 192] @ [192 x 128] + bias, relu
    u64 a01[4], a23[4];
    {
        ulonglong2 b1 = ((const ulonglong2*)be1)[lane];
        #pragma unroll
        for (int j = 0; j < 4; j++) { a01[j] = b1.x; a23[j] = b1.y; }
    }
    #pragma unroll 4
    for (int k = 0; k < 192; k++) {
        ulonglong2 w = ((const ulonglong2*)g_W1t)[k * 32 + lane];
        #pragma unroll
        for (int j = 0; j < 4; j++) {
            u64 s = *(const u64*)&s_in[warp][j][k];
            a01[j] = ffma2(w.x, s, a01[j]);
            a23[j] = ffma2(w.y, s, a23[j]);
        }
    }
    __syncwarp();   // all GEMM1 reads done before overwriting region
    #pragma unroll
    for (int j = 0; j < 4; j++) {
        float2 p0 = unpack2(a01[j]), p1 = unpack2(a23[j]);
        s_in[warp][j][4*lane+0] = make_float2(fmaxf(p0.x,0.f), fmaxf(p0.x,0.f));
        s_in[warp][j][4*lane+1] = make_float2(fmaxf(p0.y,0.f), fmaxf(p0.y,0.f));
        s_in[warp][j][4*lane+2] = make_float2(fmaxf(p1.x,0.f), fmaxf(p1.x,0.f));
        s_in[warp][j][4*lane+3] = make_float2(fmaxf(p1.y,0.f), fmaxf(p1.y,0.f));
    }
    __syncwarp();

    // GEMM2: [4 x 128] @ [128 x 128] + bias
    {
        ulonglong2 b2 = ((const ulonglong2*)be2)[lane];
        #pragma unroll
        for (int j = 0; j < 4; j++) { a01[j] = b2.x; a23[j] = b2.y; }
    }
    #pragma unroll 4
    for (int k = 0; k < 128; k++) {
        ulonglong2 w = ((const ulonglong2*)g_W2t)[k * 32 + lane];
        #pragma unroll
        for (int j = 0; j < 4; j++) {
            u64 s = *(const u64*)&s_in[warp][j][k];
            a01[j] = ffma2(w.x, s, a01[j]);
            a23[j] = ffma2(w.y, s, a23[j]);
        }
    }
    #pragma unroll
    for (int j = 0; j < 4; j++) {
        float2 p0 = unpack2(a01[j]), p1 = unpack2(a23[j]);
        g_edge_msg[(e0 + j) * 32 + lane] = make_float4(p0.x, p0.y, p1.x, p1.y);
    }
}

// ---------------- node MLP + residual + relu + layernorm (packed f32x2) ------
__global__ void __launch_bounds__(256) k_node(const float4* __restrict__ xh,
                                              const float* __restrict__ bp,
                                              const float* __restrict__ bn1,
                                              const float* __restrict__ bn2,
                                              const float4* __restrict__ gamma4,
                                              const float4* __restrict__ beta4,
                                              float4* __restrict__ out) {
    __shared__ float2 s_buf[8][4][128];  // 32KB
    int warp = threadIdx.x >> 5, lane = threadIdx.x & 31;
    int n0 = (blockIdx.x * 8 + warp) * 4;

    // --- p = Wp @ x + bp  (stage x duplicated) ---
    #pragma unroll
    for (int j = 0; j < 4; j++) {
        float4 a = xh[(n0 + j) * 32 + lane];
        s_buf[warp][j][4*lane+0] = make_float2(a.x, a.x);
        s_buf[warp][j][4*lane+1] = make_float2(a.y, a.y);
        s_buf[warp][j][4*lane+2] = make_float2(a.z, a.z);
        s_buf[warp][j][4*lane+3] = make_float2(a.w, a.w);
    }
    __syncwarp();

    u64 p01[4], p23[4];
    {
        ulonglong2 b = ((const ulonglong2*)bp)[lane];
        #pragma unroll
        for (int j = 0; j < 4; j++) { p01[j] = b.x; p23[j] = b.y; }
    }
    #pragma unroll 4
    for (int k = 0; k < 128; k++) {
        ulonglong2 w = ((const ulonglong2*)g_Wpt)[k * 32 + lane];
        #pragma unroll
        for (int j = 0; j < 4; j++) {
            u64 s = *(const u64*)&s_buf[warp][j][k];
            p01[j] = ffma2(w.x, s, p01[j]);
            p23[j] = ffma2(w.y, s, p23[j]);
        }
    }
    __syncwarp();

    // --- stage node_msg = node_acc / cnt (duplicated) ---
    #pragma unroll
    for (int j = 0; j < 4; j++) {
        int n = n0 + j;
        float inv = 1.f / fmaxf(g_node_cnt[n], 1.f);
        float4 a = g_node_acc[n * 32 + lane];
        s_buf[warp][j][4*lane+0] = make_float2(a.x*inv, a.x*inv);
        s_buf[warp][j][4*lane+1] = make_float2(a.y*inv, a.y*inv);
        s_buf[warp][j][4*lane+2] = make_float2(a.z*inv, a.z*inv);
        s_buf[warp][j][4*lane+3] = make_float2(a.w*inv, a.w*inv);
    }
    __syncwarp();

    // --- t = relu(Wn1 @ m + bn1) ---
    u64 a01[4], a23[4];
    {
        ulonglong2 b = ((const ulonglong2*)bn1)[lane];
        #pragma unroll
        for (int j = 0; j < 4; j++) { a01[j] = b.x; a23[j] = b.y; }
    }
    #pragma unroll 4
    for (int k = 0; k < 128; k++) {
        ulonglong2 w = ((const ulonglong2*)g_Wn1t)[k * 32 + lane];
        #pragma unroll
        for (int j = 0; j < 4; j++) {
            u64 s = *(const u64*)&s_buf[warp][j][k];
            a01[j] = ffma2(w.x, s, a01[j]);
            a23[j] = ffma2(w.y, s, a23[j]);
        }
    }
    __syncwarp();
    #pragma unroll
    for (int j = 0; j < 4; j++) {
        float2 p0 = unpack2(a01[j]), p1 = unpack2(a23[j]);
        s_buf[warp][j][4*lane+0] = make_float2(fmaxf(p0.x,0.f), fmaxf(p0.x,0.f));
        s_buf[warp][j][4*lane+1] = make_float2(fmaxf(p0.y,0.f), fmaxf(p0.y,0.f));
        s_buf[warp][j][4*lane+2] = make_float2(fmaxf(p1.x,0.f), fmaxf(p1.x,0.f));
        s_buf[warp][j][4*lane+3] = make_float2(fmaxf(p1.y,0.f), fmaxf(p1.y,0.f));
    }
    __syncwarp();

    // --- u = Wn2 @ t + bn2 ; z = relu(p + u) ; layernorm ---
    {
        ulonglong2 b = ((const ulonglong2*)bn2)[lane];
        #pragma unroll
        for (int j = 0; j < 4; j++) { a01[j] = b.x; a23[j] = b.y; }
    }
    #pragma unroll 4
    for (int k = 0; k < 128; k++) {
        ulonglong2 w = ((const ulonglong2*)g_Wn2t)[k * 32 + lane];
        #pragma unroll
        for (int j = 0; j < 4; j++) {
            u64 s = *(const u64*)&s_buf[warp][j][k];
            a01[j] = ffma2(w.x, s, a01[j]);
            a23[j] = ffma2(w.y, s, a23[j]);
        }
    }

    float4 g = gamma4[lane], b = beta4[lane];
    #pragma unroll
    for (int j = 0; j < 4; j++) {
        float2 u0 = unpack2(a01[j]), u1 = unpack2(a23[j]);
        float2 q0 = unpack2(p01[j]), q1 = unpack2(p23[j]);
        float4 z = make_float4(fmaxf(q0.x + u0.x, 0.f),
                               fmaxf(q0.y + u0.y, 0.f),
                               fmaxf(q1.x + u1.x, 0.f),
                               fmaxf(q1.y + u1.y, 0.f));
        float s  = z.x + z.y + z.z + z.w;
        float q  = z.x*z.x + z.y*z.y + z.z*z.z + z.w*z.w;
        #pragma unroll
        for (int o = 16; o > 0; o >>= 1) {
            s += __shfl_xor_sync(0xFFFFFFFFu, s, o);
            q += __shfl_xor_sync(0xFFFFFFFFu, q, o);
        }
        float mu  = s * (1.f / 128.f);
        float var = q * (1.f / 128.f) - mu * mu;
        float r   = rsqrtf(var + 1e-5f);
        out[(n0 + j) * 32 + lane] =
            make_float4((z.x - mu) * r * g.x + b.x, (z.y - mu) * r * g.y + b.y,
                        (z.z - mu) * r * g.z + b.z, (z.w - mu) * r * g.w + b.w);
    }
}

// ---------------- launch -----------------------------------------------------
extern "C" void kernel_launch(void* const* d_in, const int* in_sizes, int n_in,
                              void* d_out, int out_size) {
    const float* x_h   = (const float*)d_in[0];
    const float* attr  = (const float*)d_in[1];
    const float* Wp    = (const float*)d_in[2];
    const float* bp    = (const float*)d_in[3];
    const float* We1   = (const float*)d_in[4];
    const float* be1   = (const float*)d_in[5];
    const float* We2   = (const float*)d_in[6];
    const float* be2   = (const float*)d_in[7];
    const float* Wn1   = (const float*)d_in[8];
    const float* bn1   = (const float*)d_in[9];
    const float* Wn2   = (const float*)d_in[10];
    const float* bn2   = (const float*)d_in[11];
    const float* gamma = (const float*)d_in[12];
    const float* beta  = (const float*)d_in[13];
    const int*   fg    = (const int*)d_in[14];
    const int*   res   = (const int*)d_in[15];

    k_zero<<<25000, 256>>>();
    k_prep<<<96, 256>>>(We1, We2, Wp, Wn1, Wn2);
    k_scat_ne<<<125000, 256>>>((const float4*)x_h, fg, res);
    k_edge_mlp<<<6250, 256>>>((const float4*)attr, be1, be2);
    k_scat_en<<<125000, 256>>>(fg, res);
    k_node<<<3125, 256>>>((const float4*)x_h, bp, bn1, bn2,
                          (const float4*)gamma, (const float4*)beta,
                          (float4*)d_out);
}

// round 7
// speedup vs baseline: 1.4049x; 1.4049x over previous
#include <cuda_runtime.h>
#include <cuda_bf16.h>

#define H  100000
#define E  200000
#define NI 1000000

typedef unsigned long long u64;

// ---------------- scratch (device globals: no allocations allowed) ----------
__device__ float4 g_edge_acc[E * 32];   // [E][128] as float4
__device__ float  g_edge_cnt[E];
__device__ float4 g_edge_msg[E * 32];   // [E][128]
__device__ float4 g_node_acc[H * 32];   // [H][128]
__device__ float  g_node_cnt[H];

// transposed weights: [k][out] so the k-loop load is lane-coalesced float4
__device__ float4 g_W1t[192 * 32];      // from We1 [128][192]
__device__ float4 g_W2t[128 * 32];      // from We2 [128][128]
__device__ float4 g_Wpt[128 * 32];      // from Wp
__device__ float4 g_Wn1t[128 * 32];
__device__ float4 g_Wn2t[128 * 32];

// ---------------- packed f32x2 helpers ---------------------------------------
__device__ __forceinline__ u64 ffma2(u64 a, u64 b, u64 c) {
    u64 d; asm("fma.rn.f32x2 %0, %1, %2, %3;" : "=l"(d) : "l"(a), "l"(b), "l"(c)); return d;
}
__device__ __forceinline__ u64 add2(u64 a, u64 b) {
    u64 d; asm("add.rn.f32x2 %0, %1, %2;" : "=l"(d) : "l"(a), "l"(b)); return d;
}
__device__ __forceinline__ u64 mul2(u64 a, u64 b) {
    u64 d; asm("mul.rn.f32x2 %0, %1, %2;" : "=l"(d) : "l"(a), "l"(b)); return d;
}
__device__ __forceinline__ u64 dup2(float f) {
    u64 d; asm("mov.b64 %0, {%1, %1};" : "=l"(d) : "f"(f)); return d;
}
__device__ __forceinline__ u64 pack2(float x, float y) {
    u64 d; asm("mov.b64 %0, {%1, %2};" : "=l"(d) : "f"(x), "f"(y)); return d;
}
__device__ __forceinline__ float2 unpack2(u64 v) {
    float2 r; asm("mov.b64 {%0, %1}, %2;" : "=f"(r.x), "=f"(r.y) : "l"(v)); return r;
}

// ---------------- zero accumulators -----------------------------------------
__global__ void k_zero() {
    int i = blockIdx.x * blockDim.x + threadIdx.x;
    float4 z = make_float4(0.f, 0.f, 0.f, 0.f);
    if (i < E * 32) g_edge_acc[i] = z;
    if (i < H * 32) g_node_acc[i] = z;
    if (i < E) g_edge_cnt[i] = 0.f;
    if (i < H) g_node_cnt[i] = 0.f;
}

// ---------------- transpose weights -----------------------------------------
__global__ void k_prep(const float* __restrict__ We1, const float* __restrict__ We2,
                       const float* __restrict__ Wp,  const float* __restrict__ Wn1,
                       const float* __restrict__ Wn2) {
    int i = blockIdx.x * blockDim.x + threadIdx.x;
    if (i < 192 * 128) {
        int k = i / 128, o = i % 128;
        ((float*)g_W1t)[i] = We1[o * 192 + k];
    }
    if (i < 128 * 128) {
        int k = i / 128, o = i % 128;
        ((float*)g_W2t)[i]  = We2[o * 128 + k];
        ((float*)g_Wpt)[i]  = Wp [o * 128 + k];
        ((float*)g_Wn1t)[i] = Wn1[o * 128 + k];
        ((float*)g_Wn2t)[i] = Wn2[o * 128 + k];
    }
}

// ---------------- vectorized global reduction helper ------------------------
__device__ __forceinline__ void red_add_v4(float* p, float4 v) {
    unsigned long long a = (unsigned long long)__cvta_generic_to_global(p);
    asm volatile("red.global.add.v4.f32 [%0], {%1, %2, %3, %4};"
                 :: "l"(a), "f"(v.x), "f"(v.y), "f"(v.z), "f"(v.w) : "memory");
}

// ---------------- scatter node -> edge ---------------------------------------
__global__ void k_scat_ne(const float4* __restrict__ xh,
                          const int* __restrict__ fg, const int* __restrict__ res) {
    int t = blockIdx.x * blockDim.x + threadIdx.x;   // < NI*32 = 32M
    int i = t >> 5, c = t & 31;
    int f = fg[i], r = res[i];
    float4 v = xh[f * 32 + c];
    red_add_v4((float*)&g_edge_acc[r * 32 + c], v);
    if (c == 0) atomicAdd(&g_edge_cnt[r], 1.f);
}

// ---------------- scatter edge -> node ---------------------------------------
__global__ void k_scat_en(const int* __restrict__ fg, const int* __restrict__ res) {
    int t = blockIdx.x * blockDim.x + threadIdx.x;
    int i = t >> 5, c = t & 31;
    int f = fg[i], r = res[i];
    float4 v = g_edge_msg[r * 32 + c];
    red_add_v4((float*)&g_node_acc[f * 32 + c], v);
    if (c == 0) atomicAdd(&g_node_cnt[f], 1.f);
}

// =============================================================================
// Edge MLP: 5 warps/block, 8 edges/warp as 4 pairs. FFMA2 with weight-dup.
// smem rows are 48B: [jp0 pair][jp1][jp2][jp3][16B pad], row-permuted
// phys(k) = (k%4)*G + k/4 so each lane's 4 k-values land in 4 separate groups.
// Per k-step: 1 LDG.128 (w) + 4 dup MOV + 2 broadcast LDS.128 + 16 FFMA2.
// =============================================================================
__global__ void __launch_bounds__(160) k_edge_mlp(const float4* __restrict__ attr,
                                                  const float* __restrict__ be1,
                                                  const float* __restrict__ be2) {
    __shared__ __align__(16) float2 s[5][192][6];   // 46080 B
    int warp = threadIdx.x >> 5, lane = threadIdx.x & 31;
    int e0 = (blockIdx.x * 5 + warp) * 8;

    // ---- stage e_in pairs: mean rows k=0..127 (G=48), attr rows k=128..191 ----
    #pragma unroll
    for (int jp = 0; jp < 4; jp++) {
        int ea = e0 + 2 * jp, eb = ea + 1;
        float inv0 = 1.f / fmaxf(g_edge_cnt[ea], 1.f);
        float inv1 = 1.f / fmaxf(g_edge_cnt[eb], 1.f);
        float4 a0 = g_edge_acc[ea * 32 + lane];
        float4 a1 = g_edge_acc[eb * 32 + lane];
        s[warp][0 * 48 + lane][jp] = make_float2(a0.x * inv0, a1.x * inv1);
        s[warp][1 * 48 + lane][jp] = make_float2(a0.y * inv0, a1.y * inv1);
        s[warp][2 * 48 + lane][jp] = make_float2(a0.z * inv0, a1.z * inv1);
        s[warp][3 * 48 + lane][jp] = make_float2(a0.w * inv0, a1.w * inv1);
        if (lane < 16) {
            float4 t0 = attr[ea * 16 + lane];
            float4 t1 = attr[eb * 16 + lane];
            // k = 128 + 4*lane + c  ->  phys = c*48 + 32 + lane
            s[warp][0 * 48 + 32 + lane][jp] = make_float2(t0.x, t1.x);
            s[warp][1 * 48 + 32 + lane][jp] = make_float2(t0.y, t1.y);
            s[warp][2 * 48 + 32 + lane][jp] = make_float2(t0.z, t1.z);
            s[warp][3 * 48 + 32 + lane][jp] = make_float2(t0.w, t1.w);
        }
    }
    __syncwarp();

    // ---- GEMM1: [8 x 192] @ [192 x 128] + bias, relu ----
    u64 acc[4][4];
    {
        float4 b = ((const float4*)be1)[lane];
        u64 b0 = dup2(b.x), b1 = dup2(b.y), b2 = dup2(b.z), b3 = dup2(b.w);
        #pragma unroll
        for (int jp = 0; jp < 4; jp++) {
            acc[0][jp] = b0; acc[1][jp] = b1; acc[2][jp] = b2; acc[3][jp] = b3;
        }
    }
    #pragma unroll 2
    for (int kb = 0; kb < 48; kb++) {
        #pragma unroll
        for (int c = 0; c < 4; c++) {
            float4 w = g_W1t[(kb * 4 + c) * 32 + lane];
            u64 w0 = dup2(w.x), w1 = dup2(w.y), w2 = dup2(w.z), w3 = dup2(w.w);
            const float2* row = s[warp][c * 48 + kb];
            ulonglong2 pA = *(const ulonglong2*)(row);       // jp0, jp1
            ulonglong2 pB = *(const ulonglong2*)(row + 2);   // jp2, jp3
            acc[0][0] = ffma2(w0, pA.x, acc[0][0]); acc[1][0] = ffma2(w1, pA.x, acc[1][0]);
            acc[2][0] = ffma2(w2, pA.x, acc[2][0]); acc[3][0] = ffma2(w3, pA.x, acc[3][0]);
            acc[0][1] = ffma2(w0, pA.y, acc[0][1]); acc[1][1] = ffma2(w1, pA.y, acc[1][1]);
            acc[2][1] = ffma2(w2, pA.y, acc[2][1]); acc[3][1] = ffma2(w3, pA.y, acc[3][1]);
            acc[0][2] = ffma2(w0, pB.x, acc[0][2]); acc[1][2] = ffma2(w1, pB.x, acc[1][2]);
            acc[2][2] = ffma2(w2, pB.x, acc[2][2]); acc[3][2] = ffma2(w3, pB.x, acc[3][2]);
            acc[0][3] = ffma2(w0, pB.y, acc[0][3]); acc[1][3] = ffma2(w1, pB.y, acc[1][3]);
            acc[2][3] = ffma2(w2, pB.y, acc[2][3]); acc[3][3] = ffma2(w3, pB.y, acc[3][3]);
        }
    }
    __syncwarp();

    // ---- relu + restage hidden (rows 0..127, G=32): o = 4*lane+i -> phys i*32+lane
    #pragma unroll
    for (int i = 0; i < 4; i++)
        #pragma unroll
        for (int jp = 0; jp < 4; jp++) {
            float2 v = unpack2(acc[i][jp]);
            s[warp][i * 32 + lane][jp] = make_float2(fmaxf(v.x, 0.f), fmaxf(v.y, 0.f));
        }
    __syncwarp();

    // ---- GEMM2: [8 x 128] @ [128 x 128] + bias ----
    {
        float4 b = ((const float4*)be2)[lane];
        u64 b0 = dup2(b.x), b1 = dup2(b.y), b2 = dup2(b.z), b3 = dup2(b.w);
        #pragma unroll
        for (int jp = 0; jp < 4; jp++) {
            acc[0][jp] = b0; acc[1][jp] = b1; acc[2][jp] = b2; acc[3][jp] = b3;
        }
    }
    #pragma unroll 2
    for (int kb = 0; kb < 32; kb++) {
        #pragma unroll
        for (int c = 0; c < 4; c++) {
            float4 w = g_W2t[(kb * 4 + c) * 32 + lane];
            u64 w0 = dup2(w.x), w1 = dup2(w.y), w2 = dup2(w.z), w3 = dup2(w.w);
            const float2* row = s[warp][c * 32 + kb];
            ulonglong2 pA = *(const ulonglong2*)(row);
            ulonglong2 pB = *(const ulonglong2*)(row + 2);
            acc[0][0] = ffma2(w0, pA.x, acc[0][0]); acc[1][0] = ffma2(w1, pA.x, acc[1][0]);
            acc[2][0] = ffma2(w2, pA.x, acc[2][0]); acc[3][0] = ffma2(w3, pA.x, acc[3][0]);
            acc[0][1] = ffma2(w0, pA.y, acc[0][1]); acc[1][1] = ffma2(w1, pA.y, acc[1][1]);
            acc[2][1] = ffma2(w2, pA.y, acc[2][1]); acc[3][1] = ffma2(w3, pA.y, acc[3][1]);
            acc[0][2] = ffma2(w0, pB.x, acc[0][2]); acc[1][2] = ffma2(w1, pB.x, acc[1][2]);
            acc[2][2] = ffma2(w2, pB.x, acc[2][2]); acc[3][2] = ffma2(w3, pB.x, acc[3][2]);
            acc[0][3] = ffma2(w0, pB.y, acc[0][3]); acc[1][3] = ffma2(w1, pB.y, acc[1][3]);
            acc[2][3] = ffma2(w2, pB.y, acc[2][3]); acc[3][3] = ffma2(w3, pB.y, acc[3][3]);
        }
    }

    // ---- write both edges of each pair ----
    #pragma unroll
    for (int jp = 0; jp < 4; jp++) {
        float2 v0 = unpack2(acc[0][jp]), v1 = unpack2(acc[1][jp]);
        float2 v2 = unpack2(acc[2][jp]), v3 = unpack2(acc[3][jp]);
        g_edge_msg[(e0 + 2 * jp)     * 32 + lane] = make_float4(v0.x, v1.x, v2.x, v3.x);
        g_edge_msg[(e0 + 2 * jp + 1) * 32 + lane] = make_float4(v0.y, v1.y, v2.y, v3.y);
    }
}

// =============================================================================
// Node MLP + residual + relu + layernorm. 8 warps/block, 8 nodes/warp (4 pairs).
// Order: Wn1@m -> relu -> Wn2@t into acc(init bp+bn2) -> Wp@x into same acc -> LN.
// =============================================================================
__global__ void __launch_bounds__(256) k_node(const float4* __restrict__ xh,
                                              const float* __restrict__ bp,
                                              const float* __restrict__ bn1,
                                              const float* __restrict__ bn2,
                                              const float4* __restrict__ gamma4,
                                              const float4* __restrict__ beta4,
                                              float4* __restrict__ out) {
    __shared__ __align__(16) float2 s[8][128][6];   // 49152 B
    int warp = threadIdx.x >> 5, lane = threadIdx.x & 31;
    int wg = blockIdx.x * 8 + warp;
    if (wg >= (H / 8)) return;                      // H = 12500 * 8
    int n0 = wg * 8;

    // ---- stage node_msg pairs (rows 0..127, G=32) ----
    #pragma unroll
    for (int jp = 0; jp < 4; jp++) {
        int na = n0 + 2 * jp, nb = na + 1;
        float inv0 = 1.f / fmaxf(g_node_cnt[na], 1.f);
        float inv1 = 1.f / fmaxf(g_node_cnt[nb], 1.f);
        float4 a0 = g_node_acc[na * 32 + lane];
        float4 a1 = g_node_acc[nb * 32 + lane];
        s[warp][0 * 32 + lane][jp] = make_float2(a0.x * inv0, a1.x * inv1);
        s[warp][1 * 32 + lane][jp] = make_float2(a0.y * inv0, a1.y * inv1);
        s[warp][2 * 32 + lane][jp] = make_float2(a0.z * inv0, a1.z * inv1);
        s[warp][3 * 32 + lane][jp] = make_float2(a0.w * inv0, a1.w * inv1);
    }
    __syncwarp();

    // ---- t = relu(Wn1 @ m + bn1) ----
    u64 a[4][4];
    {
        float4 b = ((const float4*)bn1)[lane];
        u64 b0 = dup2(b.x), b1 = dup2(b.y), b2 = dup2(b.z), b3 = dup2(b.w);
        #pragma unroll
        for (int jp = 0; jp < 4; jp++) {
            a[0][jp] = b0; a[1][jp] = b1; a[2][jp] = b2; a[3][jp] = b3;
        }
    }
    #pragma unroll 2
    for (int kb = 0; kb < 32; kb++) {
        #pragma unroll
        for (int c = 0; c < 4; c++) {
            float4 w = g_Wn1t[(kb * 4 + c) * 32 + lane];
            u64 w0 = dup2(w.x), w1 = dup2(w.y), w2 = dup2(w.z), w3 = dup2(w.w);
            const float2* row = s[warp][c * 32 + kb];
            ulonglong2 pA = *(const ulonglong2*)(row);
            ulonglong2 pB = *(const ulonglong2*)(row + 2);
            a[0][0] = ffma2(w0, pA.x, a[0][0]); a[1][0] = ffma2(w1, pA.x, a[1][0]);
            a[2][0] = ffma2(w2, pA.x, a[2][0]); a[3][0] = ffma2(w3, pA.x, a[3][0]);
            a[0][1] = ffma2(w0, pA.y, a[0][1]); a[1][1] = ffma2(w1, pA.y, a[1][1]);
            a[2][1] = ffma2(w2, pA.y, a[2][1]); a[3][1] = ffma2(w3, pA.y, a[3][1]);
            a[0][2] = ffma2(w0, pB.x, a[0][2]); a[1][2] = ffma2(w1, pB.x, a[1][2]);
            a[2][2] = ffma2(w2, pB.x, a[2][2]); a[3][2] = ffma2(w3, pB.x, a[3][2]);
            a[0][3] = ffma2(w0, pB.y, a[0][3]); a[1][3] = ffma2(w1, pB.y, a[1][3]);
            a[2][3] = ffma2(w2, pB.y, a[2][3]); a[3][3] = ffma2(w3, pB.y, a[3][3]);
        }
    }
    __syncwarp();
    #pragma unroll
    for (int i = 0; i < 4; i++)
        #pragma unroll
        for (int jp = 0; jp < 4; jp++) {
            float2 v = unpack2(a[i][jp]);
            s[warp][i * 32 + lane][jp] = make_float2(fmaxf(v.x, 0.f), fmaxf(v.y, 0.f));
        }
    __syncwarp();

    // ---- acc = Wn2 @ t + (bn2 + bp) ----
    u64 p[4][4];
    {
        float4 b2 = ((const float4*)bn2)[lane];
        float4 bq = ((const float4*)bp)[lane];
        u64 b0 = dup2(b2.x + bq.x), b1 = dup2(b2.y + bq.y);
        u64 b2d = dup2(b2.z + bq.z), b3 = dup2(b2.w + bq.w);
        #pragma unroll
        for (int jp = 0; jp < 4; jp++) {
            p[0][jp] = b0; p[1][jp] = b1; p[2][jp] = b2d; p[3][jp] = b3;
        }
    }
    #pragma unroll 2
    for (int kb = 0; kb < 32; kb++) {
        #pragma unroll
        for (int c = 0; c < 4; c++) {
            float4 w = g_Wn2t[(kb * 4 + c) * 32 + lane];
            u64 w0 = dup2(w.x), w1 = dup2(w.y), w2 = dup2(w.z), w3 = dup2(w.w);
            const float2* row = s[warp][c * 32 + kb];
            ulonglong2 pA = *(const ulonglong2*)(row);
            ulonglong2 pB = *(const ulonglong2*)(row + 2);
            p[0][0] = ffma2(w0, pA.x, p[0][0]); p[1][0] = ffma2(w1, pA.x, p[1][0]);
            p[2][0] = ffma2(w2, pA.x, p[2][0]); p[3][0] = ffma2(w3, pA.x, p[3][0]);
            p[0][1] = ffma2(w0, pA.y, p[0][1]); p[1][1] = ffma2(w1, pA.y, p[1][1]);
            p[2][1] = ffma2(w2, pA.y, p[2][1]); p[3][1] = ffma2(w3, pA.y, p[3][1]);
            p[0][2] = ffma2(w0, pB.x, p[0][2]); p[1][2] = ffma2(w1, pB.x, p[1][2]);
            p[2][2] = ffma2(w2, pB.x, p[2][2]); p[3][2] = ffma2(w3, pB.x, p[3][2]);
            p[0][3] = ffma2(w0, pB.y, p[0][3]); p[1][3] = ffma2(w1, pB.y, p[1][3]);
            p[2][3] = ffma2(w2, pB.y, p[2][3]); p[3][3] = ffma2(w3, pB.y, p[3][3]);
        }
    }
    __syncwarp();

    // ---- stage x pairs, accumulate Wp @ x into p ----
    #pragma unroll
    for (int jp = 0; jp < 4; jp++) {
        int na = n0 + 2 * jp, nb = na + 1;
        float4 a0 = xh[na * 32 + lane];
        float4 a1 = xh[nb * 32 + lane];
        s[warp][0 * 32 + lane][jp] = make_float2(a0.x, a1.x);
        s[warp][1 * 32 + lane][jp] = make_float2(a0.y, a1.y);
        s[warp][2 * 32 + lane][jp] = make_float2(a0.z, a1.z);
        s[warp][3 * 32 + lane][jp] = make_float2(a0.w, a1.w);
    }
    __syncwarp();
    #pragma unroll 2
    for (int kb = 0; kb < 32; kb++) {
        #pragma unroll
        for (int c = 0; c < 4; c++) {
            float4 w = g_Wpt[(kb * 4 + c) * 32 + lane];
            u64 w0 = dup2(w.x), w1 = dup2(w.y), w2 = dup2(w.z), w3 = dup2(w.w);
            const float2* row = s[warp][c * 32 + kb];
            ulonglong2 pA = *(const ulonglong2*)(row);
            ulonglong2 pB = *(const ulonglong2*)(row + 2);
            p[0][0] = ffma2(w0, pA.x, p[0][0]); p[1][0] = ffma2(w1, pA.x, p[1][0]);
            p[2][0] = ffma2(w2, pA.x, p[2][0]); p[3][0] = ffma2(w3, pA.x, p[3][0]);
            p[0][1] = ffma2(w0, pA.y, p[0][1]); p[1][1] = ffma2(w1, pA.y, p[1][1]);
            p[2][1] = ffma2(w2, pA.y, p[2][1]); p[3][1] = ffma2(w3, pA.y, p[3][1]);
            p[0][2] = ffma2(w0, pB.x, p[0][2]); p[1][2] = ffma2(w1, pB.x, p[1][2]);
            p[2][2] = ffma2(w2, pB.x, p[2][2]); p[3][2] = ffma2(w3, pB.x, p[3][2]);
            p[0][3] = ffma2(w0, pB.y, p[0][3]); p[1][3] = ffma2(w1, pB.y, p[1][3]);
            p[2][3] = ffma2(w2, pB.y, p[2][3]); p[3][3] = ffma2(w3, pB.y, p[3][3]);
        }
    }

    // ---- z = relu(p); layernorm per row (paired, 64-bit shuffles) ----
    float4 gm = gamma4[lane], bt = beta4[lane];
    #pragma unroll
    for (int jp = 0; jp < 4; jp++) {
        u64 z[4];
        #pragma unroll
        for (int i = 0; i < 4; i++) {
            float2 v = unpack2(p[i][jp]);
            z[i] = pack2(fmaxf(v.x, 0.f), fmaxf(v.y, 0.f));
        }
        u64 su = add2(add2(z[0], z[1]), add2(z[2], z[3]));
        u64 qu = ffma2(z[0], z[0], ffma2(z[1], z[1], ffma2(z[2], z[2], mul2(z[3], z[3]))));
        #pragma unroll
        for (int o = 16; o > 0; o >>= 1) {
            su = add2(su, __shfl_xor_sync(0xFFFFFFFFu, su, o));
            qu = add2(qu, __shfl_xor_sync(0xFFFFFFFFu, qu, o));
        }
        float2 sm = unpack2(su), qm = unpack2(qu);
        float mu0 = sm.x * (1.f / 128.f), mu1 = sm.y * (1.f / 128.f);
        float r0 = rsqrtf(qm.x * (1.f / 128.f) - mu0 * mu0 + 1e-5f);
        float r1 = rsqrtf(qm.y * (1.f / 128.f) - mu1 * mu1 + 1e-5f);
        float2 c0 = unpack2(z[0]), c1 = unpack2(z[1]), c2 = unpack2(z[2]), c3 = unpack2(z[3]);
        out[(n0 + 2 * jp) * 32 + lane] =
            make_float4((c0.x - mu0) * r0 * gm.x + bt.x, (c1.x - mu0) * r0 * gm.y + bt.y,
                        (c2.x - mu0) * r0 * gm.z + bt.z, (c3.x - mu0) * r0 * gm.w + bt.w);
        out[(n0 + 2 * jp + 1) * 32 + lane] =
            make_float4((c0.y - mu1) * r1 * gm.x + bt.x, (c1.y - mu1) * r1 * gm.y + bt.y,
                        (c2.y - mu1) * r1 * gm.z + bt.z, (c3.y - mu1) * r1 * gm.w + bt.w);
    }
}

// ---------------- launch -----------------------------------------------------
extern "C" void kernel_launch(void* const* d_in, const int* in_sizes, int n_in,
                              void* d_out, int out_size) {
    const float* x_h   = (const float*)d_in[0];
    const float* attr  = (const float*)d_in[1];
    const float* Wp    = (const float*)d_in[2];
    const float* bp    = (const float*)d_in[3];
    const float* We1   = (const float*)d_in[4];
    const float* be1   = (const float*)d_in[5];
    const float* We2   = (const float*)d_in[6];
    const float* be2   = (const float*)d_in[7];
    const float* Wn1   = (const float*)d_in[8];
    const float* bn1   = (const float*)d_in[9];
    const float* Wn2   = (const float*)d_in[10];
    const float* bn2   = (const float*)d_in[11];
    const float* gamma = (const float*)d_in[12];
    const float* beta  = (const float*)d_in[13];
    const int*   fg    = (const int*)d_in[14];
    const int*   res   = (const int*)d_in[15];

    k_zero<<<25000, 256>>>();
    k_prep<<<96, 256>>>(We1, We2, Wp, Wn1, Wn2);
    k_scat_ne<<<125000, 256>>>((const float4*)x_h, fg, res);
    k_edge_mlp<<<5000, 160>>>((const float4*)attr, be1, be2);   // 40 edges/block
    k_scat_en<<<125000, 256>>>(fg, res);
    k_node<<<1563, 256>>>((const float4*)x_h, bp, bn1, bn2,
                          (const float4*)gamma, (const float4*)beta,
                          (float4*)d_out);
}